// round 15
// baseline (speedup 1.0000x reference)
#include <cuda_runtime.h>
#include <cuda_fp16.h>
#include <cuda_bf16.h>

#define N_NODES 100000
#define N_EDGES 1600000
#define IN_DIM  512
#define OUT_DIM 64
#define SCAN_NB ((N_NODES + 255) / 256)   // 391 scan blocks

// ---------------- scratch (device globals: no allocation allowed) ----------
__device__ int   g_is64;                    // 1 if edge_index is int64, else int32
__device__ int   g_deg [N_NODES];           // in-degree (excl. self loop)
__device__ int   g_loc [N_NODES];           // intra-block exclusive prefix
__device__ int   g_blk [SCAN_NB];           // per-block totals
__device__ int   g_bb  [SCAN_NB];           // per-block exclusive bases
__device__ int   g_off [N_NODES];           // CSR row offsets (by dst)
__device__ int   g_cur [N_NODES];           // fill cursors
__device__ float g_dinv[N_NODES];           // (deg+1)^{-1/2} incl self loop
__device__ int   g_srcs[N_EDGES];           // edge sources grouped by dst
__device__ __align__(16) __half2 g_h2[(size_t)N_NODES * (OUT_DIM / 2)]; // h fp16

// ---------------- tf32 / async helpers --------------------------------------
__device__ __forceinline__ unsigned f2tf32(float x) {
    unsigned u;
    asm("cvt.rna.tf32.f32 %0, %1;" : "=r"(u) : "f"(x));
    return u;
}

__device__ __forceinline__ void mma_tf32(float c[4],
                                         unsigned a0, unsigned a1,
                                         unsigned a2, unsigned a3,
                                         unsigned b0, unsigned b1) {
    asm("mma.sync.aligned.m16n8k8.row.col.f32.tf32.tf32.f32 "
        "{%0,%1,%2,%3}, {%4,%5,%6,%7}, {%8,%9}, {%0,%1,%2,%3};"
        : "+f"(c[0]), "+f"(c[1]), "+f"(c[2]), "+f"(c[3])
        : "r"(a0), "r"(a1), "r"(a2), "r"(a3), "r"(b0), "r"(b1));
}

__device__ __forceinline__ void cp16(void* smem_dst, const void* gmem_src) {
    unsigned s = (unsigned)__cvta_generic_to_shared(smem_dst);
    asm volatile("cp.async.ca.shared.global [%0], [%1], 16;" :: "r"(s), "l"(gmem_src));
}
__device__ __forceinline__ void cp_commit() {
    asm volatile("cp.async.commit_group;");
}

// ---------------- 0. dtype detection ---------------------------------------
__global__ void k_detect(const long long* __restrict__ ei) {
    if (threadIdx.x == 0 && blockIdx.x == 0) {
        int ok = 1;
        for (int i = 0; i < 16; i++) {
            long long v = ei[i];
            if (v < 0 || v >= N_NODES) ok = 0;
        }
        g_is64 = ok;
    }
}

__device__ __forceinline__ int load_idx(const void* ei, long long pos, int is64) {
    if (is64) return (int)((const long long*)ei)[pos];
    return ((const int*)ei)[pos];
}

// ---------------- 1. degree histogram ---------------------------------------
__global__ void k_zero() {
    int i = blockIdx.x * blockDim.x + threadIdx.x;
    if (i < N_NODES) g_deg[i] = 0;
}

__global__ void k_hist(const void* __restrict__ ei) {
    int e = blockIdx.x * blockDim.x + threadIdx.x;
    if (e < N_EDGES) {
        int d = load_idx(ei, (long long)N_EDGES + e, g_is64);
        atomicAdd(&g_deg[d], 1);
    }
}

// ---------------- 2. hierarchical exclusive scan of g_deg -------------------
__global__ void k_scan1() {
    __shared__ int sh[256];
    const int b = blockIdx.x, t = threadIdx.x;
    const int i = b * 256 + t;
    int v = (i < N_NODES) ? g_deg[i] : 0;
    sh[t] = v;
    __syncthreads();
#pragma unroll
    for (int d = 1; d < 256; d <<= 1) {
        int u = (t >= d) ? sh[t - d] : 0;
        __syncthreads();
        sh[t] += u;
        __syncthreads();
    }
    if (i < N_NODES) g_loc[i] = sh[t] - v;
    if (t == 255)    g_blk[b] = sh[255];
}

__global__ void k_scan2() {
    __shared__ int sh[512];
    const int t = threadIdx.x;
    int v = (t < SCAN_NB) ? g_blk[t] : 0;
    sh[t] = v;
    __syncthreads();
#pragma unroll
    for (int d = 1; d < 512; d <<= 1) {
        int u = (t >= d) ? sh[t - d] : 0;
        __syncthreads();
        sh[t] += u;
        __syncthreads();
    }
    if (t < SCAN_NB) g_bb[t] = sh[t] - v;
}

__global__ void k_scan3() {
    const int i = blockIdx.x * 256 + threadIdx.x;
    if (i < N_NODES) {
        int off = g_bb[blockIdx.x] + g_loc[i];
        g_off[i] = off;
        g_cur[i] = off;
        g_dinv[i] = rsqrtf((float)(g_deg[i] + 1));  // +1 = self loop
    }
}

// ---------------- 3. CSR fill ----------------------------------------------
__global__ void k_fill(const void* __restrict__ ei) {
    int e = blockIdx.x * blockDim.x + threadIdx.x;
    if (e < N_EDGES) {
        int is64 = g_is64;
        int s = load_idx(ei, e, is64);
        int d = load_idx(ei, (long long)N_EDGES + e, is64);
        int p = atomicAdd(&g_cur[d], 1);
        g_srcs[p] = s;
    }
}

// ---------------- 4. GEMM  h = X @ W  (tf32 mma + cp.async double buffer) ---
#define BM  128
#define BN  64
#define BKT 16
#define NT  (IN_DIM / BKT)   // 32 k-tiles
#define XS_STRIDE 20         // 16 + 4 pad (80 B/row, 16B aligned)
#define WS_STRIDE 72         // 64 + 8 pad (288 B/row, 16B aligned)

__global__ void __launch_bounds__(256) k_gemm(const float* __restrict__ X,
                                              const float* __restrict__ W) {
    __shared__ __align__(16) float xs[2][BM * XS_STRIDE];
    __shared__ __align__(16) float ws[2][BKT * WS_STRIDE];

    const int tid  = threadIdx.x;
    const int wid  = tid >> 5;
    const int lane = tid & 31;
    const int wm   = wid >> 1;       // 0..3
    const int wn   = wid & 1;        // 0..1
    const int lr   = lane >> 2;      // 0..7
    const int lc   = lane & 3;       // 0..3
    const int brow = blockIdx.x * BM;

    const int xrow0 = tid >> 2;
    const int xrow1 = (tid + 256) >> 2;
    const int xq    = (tid & 3) << 2;
    const int wk    = tid >> 4;
    const int wn4   = (tid & 15) << 2;
    const int xrc0  = min(brow + xrow0, N_NODES - 1);
    const int xrc1  = min(brow + xrow1, N_NODES - 1);

    float acc[2][4][4];
#pragma unroll
    for (int i = 0; i < 2; i++)
#pragma unroll
        for (int j = 0; j < 4; j++)
#pragma unroll
            for (int q = 0; q < 4; q++) acc[i][j][q] = 0.0f;

    auto stage = [&](int st, int kt) {
        cp16(&xs[st][xrow0 * XS_STRIDE + xq], X + (size_t)xrc0 * IN_DIM + kt + xq);
        cp16(&xs[st][xrow1 * XS_STRIDE + xq], X + (size_t)xrc1 * IN_DIM + kt + xq);
        cp16(&ws[st][wk * WS_STRIDE + wn4],   W + (size_t)(kt + wk) * BN + wn4);
        cp_commit();
    };

    stage(0, 0);

    for (int it = 0; it < NT; ++it) {
        if (it + 1 < NT) {
            stage((it + 1) & 1, (it + 1) * BKT);
            asm volatile("cp.async.wait_group 1;");
        } else {
            asm volatile("cp.async.wait_group 0;");
        }
        __syncthreads();

        const int st = it & 1;
#pragma unroll
        for (int k8 = 0; k8 < 2; k8++) {
            const int kb = k8 * 8;
            unsigned a[2][4], b[4][2];
#pragma unroll
            for (int sm2 = 0; sm2 < 2; sm2++) {
                int r0 = wm * 32 + sm2 * 16 + lr;
                a[sm2][0] = f2tf32(xs[st][(r0    ) * XS_STRIDE + kb + lc    ]);
                a[sm2][1] = f2tf32(xs[st][(r0 + 8) * XS_STRIDE + kb + lc    ]);
                a[sm2][2] = f2tf32(xs[st][(r0    ) * XS_STRIDE + kb + lc + 4]);
                a[sm2][3] = f2tf32(xs[st][(r0 + 8) * XS_STRIDE + kb + lc + 4]);
            }
#pragma unroll
            for (int sn = 0; sn < 4; sn++) {
                int n = wn * 32 + sn * 8 + lr;
                b[sn][0] = f2tf32(ws[st][(kb + lc    ) * WS_STRIDE + n]);
                b[sn][1] = f2tf32(ws[st][(kb + lc + 4) * WS_STRIDE + n]);
            }
#pragma unroll
            for (int sm2 = 0; sm2 < 2; sm2++)
#pragma unroll
                for (int sn = 0; sn < 4; sn++)
                    mma_tf32(acc[sm2][sn],
                             a[sm2][0], a[sm2][1], a[sm2][2], a[sm2][3],
                             b[sn][0], b[sn][1]);
        }
        __syncthreads();
    }

    // ---- store h as fp16 pairs (col pairs are contiguous) ------------------
#pragma unroll
    for (int sm2 = 0; sm2 < 2; sm2++) {
#pragma unroll
        for (int sn = 0; sn < 4; sn++) {
            int row  = brow + wm * 32 + sm2 * 16 + lr;
            int colp = (wn * 32 + sn * 8 + lc * 2) >> 1;   // half2 index
            if (row < N_NODES)
                g_h2[(size_t)row * 32 + colp] =
                    __floats2half2_rn(acc[sm2][sn][0], acc[sm2][sn][1]);
            if (row + 8 < N_NODES)
                g_h2[(size_t)(row + 8) * 32 + colp] =
                    __floats2half2_rn(acc[sm2][sn][2], acc[sm2][sn][3]);
        }
    }
}

// ---------------- 5. aggregation + self loop + bias + log_softmax -----------
// One warp per node; 8x unrolled; fp16 h gathers (half L2 traffic).
__global__ void k_agg(const float* __restrict__ bias, float* __restrict__ out) {
    int w    = (blockIdx.x * blockDim.x + threadIdx.x) >> 5;
    int lane = threadIdx.x & 31;
    if (w >= N_NODES) return;

    const float    dn  = g_dinv[w];
    const int      beg = g_off[w];
    const int      end = beg + g_deg[w];
    const __half2* h2  = g_h2;

    float ax = 0.f, ay = 0.f;
    int e = beg;
    for (; e + 8 <= end; e += 8) {
        int s0 = g_srcs[e];
        int s1 = g_srcs[e + 1];
        int s2 = g_srcs[e + 2];
        int s3 = g_srcs[e + 3];
        int s4 = g_srcs[e + 4];
        int s5 = g_srcs[e + 5];
        int s6 = g_srcs[e + 6];
        int s7 = g_srcs[e + 7];
        float w0 = g_dinv[s0], w1 = g_dinv[s1], w2 = g_dinv[s2], w3 = g_dinv[s3];
        float w4 = g_dinv[s4], w5 = g_dinv[s5], w6 = g_dinv[s6], w7 = g_dinv[s7];
        float2 v0 = __half22float2(h2[(size_t)s0 * 32 + lane]);
        float2 v1 = __half22float2(h2[(size_t)s1 * 32 + lane]);
        float2 v2 = __half22float2(h2[(size_t)s2 * 32 + lane]);
        float2 v3 = __half22float2(h2[(size_t)s3 * 32 + lane]);
        float2 v4 = __half22float2(h2[(size_t)s4 * 32 + lane]);
        float2 v5 = __half22float2(h2[(size_t)s5 * 32 + lane]);
        float2 v6 = __half22float2(h2[(size_t)s6 * 32 + lane]);
        float2 v7 = __half22float2(h2[(size_t)s7 * 32 + lane]);
        w0 *= dn; w1 *= dn; w2 *= dn; w3 *= dn;
        w4 *= dn; w5 *= dn; w6 *= dn; w7 *= dn;
        ax = fmaf(v0.x, w0, ax); ay = fmaf(v0.y, w0, ay);
        ax = fmaf(v1.x, w1, ax); ay = fmaf(v1.y, w1, ay);
        ax = fmaf(v2.x, w2, ax); ay = fmaf(v2.y, w2, ay);
        ax = fmaf(v3.x, w3, ax); ay = fmaf(v3.y, w3, ay);
        ax = fmaf(v4.x, w4, ax); ay = fmaf(v4.y, w4, ay);
        ax = fmaf(v5.x, w5, ax); ay = fmaf(v5.y, w5, ay);
        ax = fmaf(v6.x, w6, ax); ay = fmaf(v6.y, w6, ay);
        ax = fmaf(v7.x, w7, ax); ay = fmaf(v7.y, w7, ay);
    }
    for (; e < end; ++e) {
        int    s  = g_srcs[e];
        float  wt = g_dinv[s] * dn;
        float2 v  = __half22float2(h2[(size_t)s * 32 + lane]);
        ax = fmaf(v.x, wt, ax);
        ay = fmaf(v.y, wt, ay);
    }
    {
        float  wt = dn * dn;                   // self loop
        float2 v  = __half22float2(h2[(size_t)w * 32 + lane]);
        ax = fmaf(v.x, wt, ax);
        ay = fmaf(v.y, wt, ay);
    }
    float2 bb = ((const float2*)bias)[lane];
    ax += bb.x;
    ay += bb.y;

    float m = fmaxf(ax, ay);
#pragma unroll
    for (int o = 16; o; o >>= 1) m = fmaxf(m, __shfl_xor_sync(0xffffffffu, m, o));
    float s = expf(ax - m) + expf(ay - m);
#pragma unroll
    for (int o = 16; o; o >>= 1) s += __shfl_xor_sync(0xffffffffu, s, o);
    float lse = m + logf(s);

    ((float2*)out)[(size_t)w * 32 + lane] = make_float2(ax - lse, ay - lse);
}

// ---------------- stream/event resources (static init: before mem checkpoints,
// no device-memory allocation APIs used) -------------------------------------
static cudaStream_t s_side = nullptr;
static cudaEvent_t  s_ev_fork = nullptr, s_ev_gemm = nullptr;
namespace {
struct ResInit {
    ResInit() {
        cudaStreamCreateWithFlags(&s_side, cudaStreamNonBlocking);
        cudaEventCreateWithFlags(&s_ev_fork, cudaEventDisableTiming);
        cudaEventCreateWithFlags(&s_ev_gemm, cudaEventDisableTiming);
    }
};
static ResInit s_res_init;
}

// ---------------- launch ----------------------------------------------------
extern "C" void kernel_launch(void* const* d_in, const int* in_sizes, int n_in,
                              void* d_out, int out_size) {
    const float* x  = (const float*)d_in[0];
    const void*  ei = d_in[1];
    const float* W  = (const float*)d_in[2];
    const float* b  = (const float*)d_in[3];
    float*       o  = (float*)d_out;

    // fork: GEMM branch (independent of edge/CSR chain) on side stream
    cudaEventRecord(s_ev_fork, 0);
    cudaStreamWaitEvent(s_side, s_ev_fork, 0);
    k_gemm<<<(N_NODES + BM - 1) / BM, 256, 0, s_side>>>(x, W);
    cudaEventRecord(s_ev_gemm, s_side);

    // main branch: edge-index / CSR chain
    k_detect<<<1, 32>>>((const long long*)ei);
    k_zero<<<(N_NODES + 255) / 256, 256>>>();
    k_hist<<<(N_EDGES + 255) / 256, 256>>>(ei);
    k_scan1<<<SCAN_NB, 256>>>();
    k_scan2<<<1, 512>>>();
    k_scan3<<<SCAN_NB, 256>>>();
    k_fill<<<(N_EDGES + 255) / 256, 256>>>(ei);

    // join, then aggregate + softmax
    cudaStreamWaitEvent(0, s_ev_gemm, 0);
    k_agg<<<(N_NODES * 32 + 255) / 256, 256>>>(b, o);
}